// round 1
// baseline (speedup 1.0000x reference)
#include <cuda_runtime.h>
#include <math.h>

// Problem constants
#define B 256
#define N 256
#define D 512
#define EPSV 1e-8f

// Scratch for lam/delta (allocation-free rule -> __device__ globals)
__device__ float g_lam[B * D];
__device__ float g_delta[B * D];

// Kernel 1: per-(b,d) reduction over n of |pd|, compute lam/beta/delta,
// write new_central and new_err. One block per batch, 512 threads (one per d).
// Reads are fully coalesced: warp reads 128 contiguous bytes per n-iteration.
__global__ __launch_bounds__(D) void k_stats(const float* __restrict__ cv,
                                             const float* __restrict__ pd,
                                             const float* __restrict__ err,
                                             float* __restrict__ out_central,
                                             float* __restrict__ out_err) {
    const int b = blockIdx.x;
    const int d = threadIdx.x;

    const float* p = pd + (size_t)b * N * D + d;
    float acc = 0.0f;
#pragma unroll 8
    for (int n = 0; n < N; n++) {
        acc += fabsf(p[(size_t)n * D]);
    }

    const int bd = b * D + d;
    const float e = err[bd];
    const float c = cv[bd];

    const float radius = acc + fabsf(e);
    const float lower = c - radius;
    const float upper = c + radius;
    const float rl = fmaxf(lower, 0.0f);
    const float ru = fmaxf(upper, 0.0f);

    float lam = (ru - rl) / (upper - lower + EPSV);
    if (lower >= 0.0f) lam = 1.0f;
    if (upper < 0.0f) lam = 0.0f;
    if (isnan(lam)) lam = 0.0f;
    lam = fminf(fmaxf(lam, 0.0f), 1.0f);

    const float beta = (rl - lam * lower) * 0.5f;
    const float delta = fabsf(beta);

    g_lam[bd] = lam;
    g_delta[bd] = delta;

    out_central[bd] = lam * c + beta;
    out_err[bd] = lam * e;
}

// Kernel 2: scaled_pd region of new_pd: out[b, n, d] = pd[b,n,d] * lam[b,d].
// float4-vectorized; 8,388,608 float4 elements total.
// new_pd layout: (B, N+D, D) -> batch stride 768*512, rows [0,256) are scaled_pd.
__global__ __launch_bounds__(256) void k_scale(const float4* __restrict__ pd4,
                                               float4* __restrict__ out_pd4) {
    const unsigned idx = blockIdx.x * blockDim.x + threadIdx.x;  // < B*N*(D/4)
    const unsigned PER_B = N * (D / 4);        // 32768
    const unsigned b = idx >> 15;              // / 32768
    const unsigned rem = idx & (PER_B - 1);    // row*128 + d4
    const unsigned d4 = rem & 127;

    const float4 v = pd4[idx];
    const float4 l = ((const float4*)g_lam)[b * (D / 4) + d4];
    float4 o;
    o.x = v.x * l.x;
    o.y = v.y * l.y;
    o.z = v.z * l.z;
    o.w = v.w * l.w;

    // output row offset within batch: rows 0..255 map directly
    out_pd4[(size_t)b * ((N + D) * (D / 4)) + rem] = o;
}

// Kernel 3: diag-embed region: out[b, 256+r, d] = (r==d) ? delta[b][r] : 0.
// float4-vectorized; 16,777,216 float4 elements; essentially a zero-fill at
// peak write BW with one sparse scalar per row.
__global__ __launch_bounds__(256) void k_diag(float4* __restrict__ out_pd4) {
    const unsigned idx = blockIdx.x * blockDim.x + threadIdx.x;  // < B*D*(D/4)
    const unsigned PER_B = D * (D / 4);        // 65536
    const unsigned b = idx >> 16;              // / 65536
    const unsigned rem = idx & (PER_B - 1);    // r*128 + d4
    const unsigned r = rem >> 7;
    const unsigned d4 = rem & 127;

    float4 o = make_float4(0.0f, 0.0f, 0.0f, 0.0f);
    const unsigned d0 = d4 << 2;
    if (r >= d0 && r < d0 + 4) {
        const float dl = g_delta[b * D + r];
        ((float*)&o)[r - d0] = dl;
    }

    // rows 256..767 within batch
    out_pd4[(size_t)b * ((N + D) * (D / 4)) + N * (D / 4) + rem] = o;
}

extern "C" void kernel_launch(void* const* d_in, const int* in_sizes, int n_in,
                              void* d_out, int out_size) {
    const float* cv = (const float*)d_in[0];   // (256, 512)
    const float* pd = (const float*)d_in[1];   // (256, 256, 512)
    const float* err = (const float*)d_in[2];  // (256, 512)

    float* out = (float*)d_out;
    // Output layout: [new_central (B*D)] [new_pd (B*(N+D)*D)] [new_err (B*D)]
    float* out_central = out;
    float* out_pd = out + (size_t)B * D;
    float* out_err = out + (size_t)B * D + (size_t)B * (N + D) * D;

    // Kernel 1: stats + small outputs
    k_stats<<<B, D>>>(cv, pd, err, out_central, out_err);

    // Kernel 2: scaled_pd (B*N*D/4 float4 = 8,388,608 -> 32768 blocks x 256)
    {
        const unsigned total4 = B * N * (D / 4);
        k_scale<<<total4 / 256, 256>>>((const float4*)pd, (float4*)out_pd);
    }

    // Kernel 3: diag region (B*D*D/4 float4 = 16,777,216 -> 65536 blocks x 256)
    {
        const unsigned total4 = B * D * (D / 4);
        k_diag<<<total4 / 256, 256>>>((float4*)out_pd);
    }
}

// round 2
// speedup vs baseline: 1.1487x; 1.1487x over previous
#include <cuda_runtime.h>
#include <math.h>

// Problem constants
#define B 256
#define N 256
#define D 512
#define EPSV 1e-8f

#define DSPLIT 4
#define DCHUNK (D / DSPLIT)   // 128 d's per block
#define DC4 (DCHUNK / 4)      // 32 float4 columns per block
#define NGROUPS 8
#define NCHUNK (N / NGROUPS)  // 32 n-rows per thread-group
// block = DC4 * NGROUPS = 256 threads

// Scratch for delta (allocation-free rule -> __device__ global)
__device__ float g_delta[B * D];

// Fused kernel: pass 1 reduces |pd| over n for a (b, d-chunk) slice (128 KB,
// streamed from DRAM into L2), computes lam/beta/delta, writes new_central/
// new_err; pass 2 re-reads the slice (L2 hit: reuse distance capped at
// 4 blocks/SM * 148 SMs * 128 KB = 75 MB < 126 MB L2) and writes scaled_pd.
__global__ __launch_bounds__(256, 4) void k_fused(const float* __restrict__ cv,
                                                  const float4* __restrict__ pd4,
                                                  const float* __restrict__ err,
                                                  float* __restrict__ out_central,
                                                  float4* __restrict__ out_pd4,
                                                  float* __restrict__ out_err) {
    const int b = blockIdx.x;
    const int h = blockIdx.y;  // d-chunk index
    const int tid = threadIdx.x;
    const int d4 = tid & (DC4 - 1);  // 0..31 (float4 column within chunk)
    const int g = tid >> 5;          // 0..7  (n-group)

    __shared__ float4 s_acc[NGROUPS][DC4];
    __shared__ float4 s_lam[DC4];

    // Base pointer for this thread's float4 column
    const float4* p = pd4 + (size_t)b * N * (D / 4) + (size_t)(g * NCHUNK) * (D / 4)
                      + h * DC4 + d4;

    // Pass 1: abs-sum over this group's 32 n-rows
    float4 acc = make_float4(0.f, 0.f, 0.f, 0.f);
#pragma unroll 8
    for (int n = 0; n < NCHUNK; n++) {
        const float4 v = p[(size_t)n * (D / 4)];
        acc.x += fabsf(v.x);
        acc.y += fabsf(v.y);
        acc.z += fabsf(v.z);
        acc.w += fabsf(v.w);
    }
    s_acc[g][d4] = acc;
    __syncthreads();

    // Combine groups + compute lam/beta/delta: threads 0..127, one d each
    if (tid < DCHUNK) {
        const int dc4 = tid >> 2;
        const int lane = tid & 3;
        float r = 0.f;
#pragma unroll
        for (int gg = 0; gg < NGROUPS; gg++)
            r += ((const float*)&s_acc[gg][dc4])[lane];

        const int bd = b * D + h * DCHUNK + tid;
        const float e = err[bd];
        const float c = cv[bd];

        const float radius = r + fabsf(e);
        const float lower = c - radius;
        const float upper = c + radius;
        const float rl = fmaxf(lower, 0.f);
        const float ru = fmaxf(upper, 0.f);

        float lam = (ru - rl) / (upper - lower + EPSV);
        if (lower >= 0.f) lam = 1.f;
        if (upper < 0.f) lam = 0.f;
        if (isnan(lam)) lam = 0.f;
        lam = fminf(fmaxf(lam, 0.f), 1.f);

        const float beta = (rl - lam * lower) * 0.5f;

        g_delta[bd] = fabsf(beta);
        out_central[bd] = lam * c + beta;
        out_err[bd] = lam * e;
        ((float*)&s_lam[dc4])[lane] = lam;
    }
    __syncthreads();

    // Pass 2: re-read slice (L2 hit) and write scaled_pd.
    // new_pd layout: (B, N+D, D); rows [0, N) are scaled_pd.
    const float4 lam4 = s_lam[d4];
    float4* o = out_pd4 + (size_t)b * ((N + D) * (D / 4)) + (size_t)(g * NCHUNK) * (D / 4)
                + h * DC4 + d4;
#pragma unroll 8
    for (int n = 0; n < NCHUNK; n++) {
        const float4 v = p[(size_t)n * (D / 4)];
        float4 w;
        w.x = v.x * lam4.x;
        w.y = v.y * lam4.y;
        w.z = v.z * lam4.z;
        w.w = v.w * lam4.w;
        o[(size_t)n * (D / 4)] = w;
    }
}

// Diag-embed region: out[b, N+r, d] = (r==d) ? delta[b][r] : 0.
// Pure write kernel, 268 MB.
__global__ __launch_bounds__(256) void k_diag(float4* __restrict__ out_pd4) {
    const unsigned idx = blockIdx.x * blockDim.x + threadIdx.x;  // < B*D*(D/4)
    const unsigned PER_B = D * (D / 4);     // 65536
    const unsigned b = idx >> 16;           // / 65536
    const unsigned rem = idx & (PER_B - 1); // r*128 + d4
    const unsigned r = rem >> 7;
    const unsigned d4 = rem & 127;

    float4 o = make_float4(0.f, 0.f, 0.f, 0.f);
    const unsigned d0 = d4 << 2;
    if (r >= d0 && r < d0 + 4) {
        ((float*)&o)[r - d0] = g_delta[b * D + r];
    }

    out_pd4[(size_t)b * ((N + D) * (D / 4)) + N * (D / 4) + rem] = o;
}

extern "C" void kernel_launch(void* const* d_in, const int* in_sizes, int n_in,
                              void* d_out, int out_size) {
    const float* cv = (const float*)d_in[0];   // (256, 512)
    const float* pd = (const float*)d_in[1];   // (256, 256, 512)
    const float* err = (const float*)d_in[2];  // (256, 512)

    float* out = (float*)d_out;
    // Output layout: [new_central (B*D)] [new_pd (B*(N+D)*D)] [new_err (B*D)]
    float* out_central = out;
    float* out_pd = out + (size_t)B * D;
    float* out_err = out + (size_t)B * D + (size_t)B * (N + D) * D;

    // Fused stats + scale
    {
        dim3 grid(B, DSPLIT);
        k_fused<<<grid, 256>>>(cv, (const float4*)pd, err,
                               out_central, (float4*)out_pd, out_err);
    }

    // Diag region (B*D*D/4 float4 = 16,777,216 -> 65536 blocks x 256)
    {
        const unsigned total4 = B * D * (D / 4);
        k_diag<<<total4 / 256, 256>>>((float4*)out_pd);
    }
}